// round 4
// baseline (speedup 1.0000x reference)
#include <cuda_runtime.h>

// Problem constants
#define TOKENS   65536          // 16*64*64
#define DDIM     256
#define KCODES   1024
#define Z_ELEMS  (TOKENS * DDIM)   // 16777216
#define BETA     0.25f
#define EPS_F    1e-5f

// Argmin kernel tiling
#define TT       64     // tokens per CTA (8 warps x 8 tokens)
#define KC       256    // code chunk (32 lanes x 8 codes)
#define DC       32     // d chunk per smem stage
#define NCHUNK   (KCODES / KC)          // 4
#define DSTAGES  (DDIM / DC)            // 8
#define NSTAGES  (NCHUNK * DSTAGES)     // 32
#define NBLK_A   (TOKENS / TT)          // 1024

// smem: zs 64KB + 2 x 32KB stage buffers = 128KB
#define SMEM_BYTES (TT * DDIM * 4 + 2 * (DC / 4) * KC * 16)

// Output layout (flattened reference tuple, float32):
//   [0 .. Z_ELEMS)                 z_q_st
//   [Z_ELEMS + 0..3]               commitment, codebook, cluster, perplexity
//   [Z_ELEMS + 4 .. +4+TOKENS)     indices (cast to float)

// Scratch (device globals: no allocations allowed)
__device__ int        g_indices[TOKENS];
__device__ int        g_counts[KCODES];
__device__ double     g_partial[NBLK_A];
__device__ float      g_e2[KCODES];
__device__ float      g_z2[TOKENS];
// codebook repacked: [d/4][k], entry = {pack(e[4q],e[4q+1]), pack(e[4q+2],e[4q+3])}
__device__ ulonglong2 g_ctp4[(DDIM / 4) * KCODES];

// ---------------------------------------------------------------------------
__global__ void vq_init_kernel() {
    int i = blockIdx.x * blockDim.x + threadIdx.x;
    if (i < KCODES) g_counts[i] = 0;
}

// ---------------------------------------------------------------------------
// prep codebook: e2[k] (sequential mul-then-add) + quad-packed transpose.
// ---------------------------------------------------------------------------
__global__ void vq_prep_cb_kernel(const float* __restrict__ cb) {
    int k = blockIdx.x * blockDim.x + threadIdx.x;
    if (k >= KCODES) return;
    const float* row = cb + (size_t)k * DDIM;
    float s = 0.0f;
    for (int d = 0; d < DDIM; d += 4) {
        float a = row[d], b = row[d + 1], c = row[d + 2], e = row[d + 3];
        s = __fadd_rn(s, __fmul_rn(a, a));
        s = __fadd_rn(s, __fmul_rn(b, b));
        s = __fadd_rn(s, __fmul_rn(c, c));
        s = __fadd_rn(s, __fmul_rn(e, e));
        float2 p01 = make_float2(a, b);
        float2 p23 = make_float2(c, e);
        ulonglong2 v;
        v.x = *reinterpret_cast<unsigned long long*>(&p01);
        v.y = *reinterpret_cast<unsigned long long*>(&p23);
        g_ctp4[(d >> 2) * KCODES + k] = v;
    }
    g_e2[k] = s;
}

// ---------------------------------------------------------------------------
// prep z2: coalesced loads via padded smem transpose, reference sum order.
// ---------------------------------------------------------------------------
__global__ void __launch_bounds__(256) vq_prep_z2_kernel(const float* __restrict__ z) {
    __shared__ float zt[32 * 257];
    const int tid  = threadIdx.x;
    const int tok0 = blockIdx.x * 32;
    const float* zb = z + (size_t)tok0 * DDIM;
    #pragma unroll
    for (int p = 0; p < 32; p++) {
        int e = tid + p * 256;
        zt[(e >> 8) * 257 + (e & 255)] = zb[e];
    }
    __syncthreads();
    if (tid < 32) {
        const float* row = &zt[tid * 257];
        float s = 0.0f;
        #pragma unroll 8
        for (int d = 0; d < DDIM; d++)
            s = __fadd_rn(s, __fmul_rn(row[d], row[d]));
        g_z2[tok0 + tid] = s;
    }
}

// ---------------------------------------------------------------------------
// fused argmin + gather + loss.
//   Warp w owns tokens tok0 + w*8 .. +7 (za loads are warp-broadcast).
//   Lane = code group: thread handles k = kc + lane + j*32, j = 0..7.
//   acc: 8 tokens x 8 codes f32x2 accumulators (128 regs), occupancy 1.
// ---------------------------------------------------------------------------
__global__ void __launch_bounds__(256, 1)
vq_argmin(const float* __restrict__ z, const float* __restrict__ cb,
          float* __restrict__ out) {
    extern __shared__ float smem[];
    float* zs = smem;                                                 // 16384 f
    ulonglong2* es = reinterpret_cast<ulonglong2*>(smem + TT * DDIM); // 2x2048 ul2

    const int tid  = threadIdx.x;
    const int lane = tid & 31;
    const int w    = tid >> 5;         // warp = token group
    const int tok0 = blockIdx.x * TT;

    // Load z tile: 4096 float4s, coalesced.
    {
        const float4* zg  = reinterpret_cast<const float4*>(z);
        float4*       zs4 = reinterpret_cast<float4*>(zs);
        #pragma unroll
        for (int p = 0; p < 16; p++) {
            int idx = tid + p * 256;
            zs4[idx] = zg[(size_t)tok0 * (DDIM / 4) + idx];
        }
    }

    float z2r[8];
    #pragma unroll
    for (int i = 0; i < 8; i++) z2r[i] = g_z2[tok0 + w * 8 + i];

    float best[8];
    int   bidx[8];
    #pragma unroll
    for (int i = 0; i < 8; i++) { best[i] = 3.4e38f; bidx[i] = 0; }

    // stage prefetch: 8 x 16B cp.async per thread (32KB stage)
    #define STAGE_LOAD(S, BUF)                                                   \
    do {                                                                         \
        int kc_ = ((S) >> 3) * KC;                                               \
        int dc_ = ((S) & 7) * DC;                                                \
        _Pragma("unroll")                                                        \
        for (int q = 0; q < 8; q++) {                                            \
            int idx_ = tid + q * 256;          /* 0..2047 */                     \
            int dph_ = idx_ >> 8;              /* 0..7   */                      \
            int c_   = idx_ & 255;             /* 0..255 */                      \
            const ulonglong2* src_ =                                             \
                &g_ctp4[(size_t)((dc_ >> 2) + dph_) * KCODES + kc_ + c_];        \
            unsigned dst_ = (unsigned)__cvta_generic_to_shared(                  \
                &es[(BUF) * 2048 + idx_]);                                       \
            asm volatile("cp.async.cg.shared.global [%0], [%1], 16;\n"           \
                         :: "r"(dst_), "l"(src_));                               \
        }                                                                        \
        asm volatile("cp.async.commit_group;\n" ::: "memory");                   \
    } while (0)

    STAGE_LOAD(0, 0);

    unsigned long long acc[8][8];
    float e2r[8];
    int buf = 0;

    for (int s = 0; s < NSTAGES; s++) {
        if ((s & 7) == 0) {
            int kc = (s >> 3) * KC;
            #pragma unroll
            for (int j = 0; j < 8; j++) {
                e2r[j] = g_e2[kc + lane + j * 32];
                #pragma unroll
                for (int i = 0; i < 8; i++) acc[i][j] = 0ull;
            }
        }

        asm volatile("cp.async.wait_group 0;\n" ::: "memory");
        __syncthreads();
        if (s + 1 < NSTAGES) STAGE_LOAD(s + 1, buf ^ 1);

        const int dc = (s & 7) * DC;
        const ulonglong2* eb_base = &es[buf * 2048];
        const float* zrow0 = zs + (w * 8) * DDIM + dc;

        #pragma unroll
        for (int dph = 0; dph < DC / 4; dph++) {     // 8 iterations of 4 d
            ulonglong2 za[8];
            #pragma unroll
            for (int i = 0; i < 8; i++)
                za[i] = *reinterpret_cast<const ulonglong2*>(
                    zrow0 + i * DDIM + 4 * dph);
            #pragma unroll
            for (int j = 0; j < 8; j++) {
                ulonglong2 eb = eb_base[dph * KC + lane + j * 32];
                #pragma unroll
                for (int i = 0; i < 8; i++) {
                    asm volatile("fma.rn.f32x2 %0, %1, %2, %0;"
                                 : "+l"(acc[i][j]) : "l"(za[i].x), "l"(eb.x));
                    asm volatile("fma.rn.f32x2 %0, %1, %2, %0;"
                                 : "+l"(acc[i][j]) : "l"(za[i].y), "l"(eb.y));
                }
            }
        }
        buf ^= 1;

        if ((s & 7) == 7) {
            int kc = (s >> 3) * KC;
            #pragma unroll
            for (int j = 0; j < 8; j++) {
                int k = kc + lane + j * 32;
                #pragma unroll
                for (int i = 0; i < 8; i++) {
                    float lo = __uint_as_float((unsigned)(acc[i][j] & 0xFFFFFFFFull));
                    float hi = __uint_as_float((unsigned)(acc[i][j] >> 32));
                    float ze = __fadd_rn(lo, hi);
                    float dist = __fsub_rn(__fadd_rn(z2r[i], e2r[j]),
                                           __fmul_rn(2.0f, ze));
                    if (dist < best[i]) { best[i] = dist; bidx[i] = k; }
                }
            }
        }
    }
    #undef STAGE_LOAD

    // --- warp-level argmin reduce per token (tokens never cross warps) ---
    __syncthreads();                      // es region free for reuse
    int*    sfin = reinterpret_cast<int*>(smem + TT * DDIM);        // 64 ints
    double* dred = reinterpret_cast<double*>(smem + TT * DDIM + 64);// 256 dbl

    #pragma unroll
    for (int i = 0; i < 8; i++) {
        float bd = best[i];
        int   bi = bidx[i];
        #pragma unroll
        for (int off = 16; off > 0; off >>= 1) {
            float od = __shfl_down_sync(0xFFFFFFFFu, bd, off);
            int   oi = __shfl_down_sync(0xFFFFFFFFu, bi, off);
            if (od < bd || (od == bd && oi < bi)) { bd = od; bi = oi; }
        }
        if (lane == 0) {
            int t  = w * 8 + i;
            int gt = tok0 + t;
            g_indices[gt] = bi;
            out[Z_ELEMS + 4 + gt] = (float)bi;
            atomicAdd(&g_counts[bi], 1);
            sfin[t] = bi;
        }
    }
    __syncthreads();

    // --- fused gather + z_q_st write + loss partial (z tile still in smem) ---
    double sacc = 0.0;
    const float4* cb4 = reinterpret_cast<const float4*>(cb);
    const float4* zs4 = reinterpret_cast<const float4*>(zs);
    float4*       o4  = reinterpret_cast<float4*>(out);
    #pragma unroll
    for (int p = 0; p < 16; p++) {
        int e4 = tid + p * 256;           // 0..4095
        int t  = e4 >> 6;
        int d4 = e4 & 63;
        int idx = sfin[t];
        float4 zq = cb4[(size_t)idx * (DDIM / 4) + d4];
        float4 zz = zs4[e4];
        float4 o;
        o.x = __fadd_rn(zz.x, __fsub_rn(zq.x, zz.x));
        o.y = __fadd_rn(zz.y, __fsub_rn(zq.y, zz.y));
        o.z = __fadd_rn(zz.z, __fsub_rn(zq.z, zz.z));
        o.w = __fadd_rn(zz.w, __fsub_rn(zq.w, zz.w));
        o4[(size_t)tok0 * (DDIM / 4) + e4] = o;
        float dx = __fsub_rn(zz.x, zq.x);
        float dy = __fsub_rn(zz.y, zq.y);
        float dz = __fsub_rn(zz.z, zq.z);
        float dw = __fsub_rn(zz.w, zq.w);
        sacc += (double)__fmul_rn(dx, dx);
        sacc += (double)__fmul_rn(dy, dy);
        sacc += (double)__fmul_rn(dz, dz);
        sacc += (double)__fmul_rn(dw, dw);
    }
    dred[tid] = sacc;
    __syncthreads();
    for (int stride = 128; stride > 0; stride >>= 1) {
        if (tid < stride) dred[tid] += dred[tid + stride];
        __syncthreads();
    }
    if (tid == 0) g_partial[blockIdx.x] = dred[0];
}

// ---------------------------------------------------------------------------
__global__ void vq_finalize(float* __restrict__ out) {
    if (threadIdx.x != 0 || blockIdx.x != 0) return;
    double S = 0.0;
    for (int b = 0; b < NBLK_A; b++) S += g_partial[b];
    float L = (float)(S / (double)Z_ELEMS);
    out[Z_ELEMS + 0] = L;                                   // commitment_loss
    out[Z_ELEMS + 1] = L;                                   // codebook_loss
    out[Z_ELEMS + 2] = __fadd_rn(L, __fmul_rn(BETA, L));    // cluster_loss
    float tot = 0.0f;
    for (int k = 0; k < KCODES; k++) tot = __fadd_rn(tot, (float)g_counts[k]);
    float denom = __fadd_rn(tot, EPS_F);
    float H = 0.0f;
    for (int k = 0; k < KCODES; k++) {
        float p = __fdiv_rn((float)g_counts[k], denom);
        H = __fadd_rn(H, __fmul_rn(p, __logf(__fadd_rn(p, EPS_F))));
    }
    out[Z_ELEMS + 3] = __expf(-H);
}

// ---------------------------------------------------------------------------
extern "C" void kernel_launch(void* const* d_in, const int* in_sizes, int n_in,
                              void* d_out, int out_size) {
    const float* z  = (const float*)d_in[0];   // [65536, 256]
    const float* cb = (const float*)d_in[1];   // [1024, 256]
    float* out = (float*)d_out;

    static_assert(SMEM_BYTES == 131072, "smem size");
    cudaFuncSetAttribute(vq_argmin, cudaFuncAttributeMaxDynamicSharedMemorySize,
                         SMEM_BYTES);

    vq_init_kernel<<<4, 256>>>();
    vq_prep_cb_kernel<<<4, 256>>>(cb);
    vq_prep_z2_kernel<<<TOKENS / 32, 256>>>(z);
    vq_argmin<<<NBLK_A, 256, SMEM_BYTES>>>(z, cb, out);
    vq_finalize<<<1, 1>>>(out);
}